// round 8
// baseline (speedup 1.0000x reference)
#include <cuda_runtime.h>
#include <cstdint>

// ---------------------------------------------------------------------------
// SpatialWindowSelfAttention (Swin window MHSA), sm_103a — Round 8
//   1) TF32 GEMM, 4 warps, 64x64 warp tile, BK=16 register-prefetch pipeline
//   2) window attention (R5 structure), f32x2 PV loop
//   3) TF32 GEMM -> d_out
// ---------------------------------------------------------------------------

#define C_DIM    256
#define QKV_DIM  768
#define N_HEADS  8
#define HEAD_DIM 32
#define IMG      256
#define TOKENS   (IMG * IMG)
#define WS       64
#define MAX_B    2

__device__ float g_qkv[MAX_B * TOKENS * QKV_DIM];
__device__ float g_y  [MAX_B * TOKENS * C_DIM];

// ---------------------------------------------------------------------------
__device__ __forceinline__ uint32_t f2tf32(float x) {
    uint32_t r;
    asm("cvt.rna.tf32.f32 %0, %1;" : "=r"(r) : "f"(x));
    return r;
}

__device__ __forceinline__ void mma_tf32(float* d, const uint32_t* a, const uint32_t* b) {
    asm volatile(
        "mma.sync.aligned.m16n8k8.row.col.f32.tf32.tf32.f32 "
        "{%0,%1,%2,%3}, {%4,%5,%6,%7}, {%8,%9}, {%0,%1,%2,%3};\n"
        : "+f"(d[0]), "+f"(d[1]), "+f"(d[2]), "+f"(d[3])
        : "r"(a[0]), "r"(a[1]), "r"(a[2]), "r"(a[3]),
          "r"(b[0]), "r"(b[1]));
}

// packed fp32x2 helpers
__device__ __forceinline__ uint64_t pack2(float lo, float hi) {
    uint64_t r; asm("mov.b64 %0, {%1, %2};" : "=l"(r) : "f"(lo), "f"(hi)); return r;
}
__device__ __forceinline__ void unpack2(uint64_t v, float& lo, float& hi) {
    asm("mov.b64 {%0, %1}, %2;" : "=f"(lo), "=f"(hi) : "l"(v));
}
__device__ __forceinline__ uint64_t fma2(uint64_t a, uint64_t b, uint64_t c) {
    uint64_t d; asm("fma.rn.f32x2 %0, %1, %2, %3;" : "=l"(d) : "l"(a), "l"(b), "l"(c));
    return d;
}

// ---------------------------------------------------------------------------
// TF32 GEMM: C[M,N] = A[M,K] @ Bw[N,K]^T + bias[N]
// BM=BN=128, BK=16. 128 threads = 4 warps (2 M x 2 N), warp tile 64x64.
// Register-prefetch pipeline: STS(cur) -> sync -> LDG(next) -> MMA(cur) -> sync.
// Smem row stride 20 words (20g+t mod 32 hits all 32 banks -> conflict-free
// fragment reads; 20 % 4 == 0 keeps 16B alignment for STS.128).
// ---------------------------------------------------------------------------
#define LDS_S 20

__global__ __launch_bounds__(128, 2)
void tf32_gemm_bias_kernel(const float* __restrict__ A,
                           const float* __restrict__ Bw,
                           const float* __restrict__ bias,
                           float* __restrict__ C,
                           int M, int N, int K)
{
    constexpr int BK = 16;
    __shared__ uint32_t As[128][LDS_S];
    __shared__ uint32_t Bs[128][LDS_S];

    const int tid  = threadIdx.x;
    const int lane = tid & 31;
    const int wid  = tid >> 5;
    const int wm   = (wid & 1) * 64;
    const int wn   = (wid >> 1) * 64;
    const int m0   = blockIdx.y * 128;
    const int n0   = blockIdx.x * 128;
    const int t    = lane & 3;
    const int g    = lane >> 2;

    // per-thread load slots (fixed across tiles): 4 float4 from each tile
    const int lrow = tid >> 2;          // f>>2 for i=0 .. +32 per i
    const int lkc  = (tid & 3) * 4;

    float acc[4][8][4];
    #pragma unroll
    for (int i = 0; i < 4; i++)
        #pragma unroll
        for (int j = 0; j < 8; j++)
            #pragma unroll
            for (int r = 0; r < 4; r++) acc[i][j][r] = 0.f;

    const int NT = K / BK;
    float4 pa[4], pb[4];

    // prefetch tile 0
    #pragma unroll
    for (int i = 0; i < 4; i++) {
        int row = lrow + i * 32;
        pa[i] = *(const float4*)(A  + (size_t)(m0 + row) * K + lkc);
        pb[i] = *(const float4*)(Bw + (size_t)(n0 + row) * K + lkc);
    }

    for (int kt = 0; kt < NT; kt++) {
        // store prefetched tile to smem (cvt at store, STS.128)
        #pragma unroll
        for (int i = 0; i < 4; i++) {
            int row = lrow + i * 32;
            uint4 ua = make_uint4(f2tf32(pa[i].x), f2tf32(pa[i].y),
                                  f2tf32(pa[i].z), f2tf32(pa[i].w));
            uint4 ub = make_uint4(f2tf32(pb[i].x), f2tf32(pb[i].y),
                                  f2tf32(pb[i].z), f2tf32(pb[i].w));
            *(uint4*)&As[row][lkc] = ua;
            *(uint4*)&Bs[row][lkc] = ub;
        }
        __syncthreads();

        // issue LDG for next tile (latency hidden under MMA section)
        if (kt + 1 < NT) {
            const int k0 = (kt + 1) * BK;
            #pragma unroll
            for (int i = 0; i < 4; i++) {
                int row = lrow + i * 32;
                pa[i] = *(const float4*)(A  + (size_t)(m0 + row) * K + k0 + lkc);
                pb[i] = *(const float4*)(Bw + (size_t)(n0 + row) * K + k0 + lkc);
            }
        }

        // MMA over current smem tile
        #pragma unroll
        for (int ks = 0; ks < 2; ks++) {
            const int kb = ks * 8;
            uint32_t a[4][4], b[8][2];
            #pragma unroll
            for (int mf = 0; mf < 4; mf++) {
                int r = wm + mf * 16 + g;
                a[mf][0] = As[r    ][kb + t];
                a[mf][1] = As[r + 8][kb + t];
                a[mf][2] = As[r    ][kb + t + 4];
                a[mf][3] = As[r + 8][kb + t + 4];
            }
            #pragma unroll
            for (int nf = 0; nf < 8; nf++) {
                int n = wn + nf * 8 + g;
                b[nf][0] = Bs[n][kb + t];
                b[nf][1] = Bs[n][kb + t + 4];
            }
            #pragma unroll
            for (int mf = 0; mf < 4; mf++)
                #pragma unroll
                for (int nf = 0; nf < 8; nf++)
                    mma_tf32(acc[mf][nf], a[mf], b[nf]);
        }
        __syncthreads();
    }

    // epilogue: bias + store
    #pragma unroll
    for (int mf = 0; mf < 4; mf++) {
        int row = m0 + wm + mf * 16 + g;
        #pragma unroll
        for (int nf = 0; nf < 8; nf++) {
            int col = n0 + wn + nf * 8 + 2 * t;
            float bx = bias[col], by = bias[col + 1];
            float2 v0 = make_float2(acc[mf][nf][0] + bx, acc[mf][nf][1] + by);
            float2 v1 = make_float2(acc[mf][nf][2] + bx, acc[mf][nf][3] + by);
            *(float2*)(C + (size_t)row * N + col)       = v0;
            *(float2*)(C + (size_t)(row + 8) * N + col) = v1;
        }
    }
}

// ---------------------------------------------------------------------------
// Window attention: block = (window, head), 64 threads.
// R5 structure (coalesced coop I/O); PV loop uses packed fma.rn.f32x2.
// ---------------------------------------------------------------------------
__global__ __launch_bounds__(64)
void win_attn_kernel(const float* __restrict__ bias_table)
{
    __shared__ float Qs[WS][HEAD_DIM];
    __shared__ float Ks[WS][HEAD_DIM];
    __shared__ float Vs[WS][HEAD_DIM];
    __shared__ float bias_s[225];

    const int t    = threadIdx.x;
    const int head = blockIdx.y;
    const int bi   = blockIdx.x >> 10;
    const int wid  = blockIdx.x & 1023;
    const int wy   = wid >> 5, wx = wid & 31;

    #pragma unroll
    for (int i = 0; i < 8; i++) {
        int slot = t + i * 64;
        int j    = slot >> 3;
        int f    = slot & 7;
        int jr = j >> 3, jc = j & 7;
        size_t tok = (size_t)bi * TOKENS + (size_t)(wy * 8 + jr) * IMG + (wx * 8 + jc);
        const float4* base = (const float4*)(g_qkv + tok * QKV_DIM + head * HEAD_DIM);
        *(float4*)&Qs[j][f * 4] = base[f];
        *(float4*)&Ks[j][f * 4] = base[f + C_DIM / 4];
        *(float4*)&Vs[j][f * 4] = base[f + 2 * C_DIM / 4];
    }
    for (int i = t; i < 225; i += 64)
        bias_s[i] = bias_table[i * N_HEADS + head];
    __syncthreads();

    const int r = t >> 3, c = t & 7;

    float q[HEAD_DIM];
    #pragma unroll
    for (int d = 0; d < HEAD_DIM; d++) q[d] = Qs[t][d];

    const float scale = 0.17677669529663689f;   // 1/sqrt(32)
    float s[WS];
    #pragma unroll
    for (int k = 0; k < WS; k++) {
        float dot = 0.f;
        #pragma unroll
        for (int d = 0; d < HEAD_DIM; d++) dot += q[d] * Ks[k][d];
        int ki = k >> 3, kj = k & 7;
        s[k] = dot * scale + bias_s[(r - ki + 7) * 15 + (c - kj + 7)];
    }

    float m = -1e30f;
    #pragma unroll
    for (int k = 0; k < WS; k++) m = fmaxf(m, s[k]);
    float sum = 0.f;
    #pragma unroll
    for (int k = 0; k < WS; k++) { s[k] = __expf(s[k] - m); sum += s[k]; }
    const float inv = 1.f / sum;

    // PV with packed f32x2 (broadcast p, pairwise V)
    uint64_t y2[HEAD_DIM / 2];
    #pragma unroll
    for (int d2 = 0; d2 < HEAD_DIM / 2; d2++) y2[d2] = 0ull;
    #pragma unroll
    for (int k = 0; k < WS; k++) {
        uint64_t p2 = pack2(s[k], s[k]);
        const uint64_t* v2 = (const uint64_t*)Vs[k];
        #pragma unroll
        for (int d2 = 0; d2 < HEAD_DIM / 2; d2++)
            y2[d2] = fma2(p2, v2[d2], y2[d2]);
    }

    // stage output in smem (reuse Qs), then coalesced cooperative store
    __syncthreads();
    #pragma unroll
    for (int d2 = 0; d2 < HEAD_DIM / 2; d2++) {
        float lo, hi; unpack2(y2[d2], lo, hi);
        Qs[t][2 * d2    ] = lo * inv;
        Qs[t][2 * d2 + 1] = hi * inv;
    }
    __syncthreads();

    #pragma unroll
    for (int i = 0; i < 8; i++) {
        int slot = t + i * 64;
        int j    = slot >> 3;
        int f    = slot & 7;
        int jr = j >> 3, jc = j & 7;
        size_t tok = (size_t)bi * TOKENS + (size_t)(wy * 8 + jr) * IMG + (wx * 8 + jc);
        float4* dst = (float4*)(g_y + tok * C_DIM + head * HEAD_DIM);
        dst[f] = *(const float4*)&Qs[j][f * 4];
    }
}

// ---------------------------------------------------------------------------
extern "C" void kernel_launch(void* const* d_in, const int* in_sizes, int n_in,
                              void* d_out, int out_size)
{
    const float *x = nullptr, *wqkv_w = nullptr, *wqkv_b = nullptr;
    const float *wp_w = nullptr, *wp_b = nullptr, *bias_table = nullptr;
    long long x_elems = 0;
    for (int i = 0; i < n_in; i++) {
        long long sz = in_sizes[i];
        if      (sz == 768LL * 256)  wqkv_w = (const float*)d_in[i];
        else if (sz == 768)          wqkv_b = (const float*)d_in[i];
        else if (sz == 256LL * 256)  wp_w   = (const float*)d_in[i];
        else if (sz == 256)          wp_b   = (const float*)d_in[i];
        else if (sz == 225LL * 8)    bias_table = (const float*)d_in[i];
        else if (sz > 1000000)       { x = (const float*)d_in[i]; x_elems = sz; }
    }

    const int B = (int)(x_elems / ((long long)TOKENS * C_DIM));   // = 2
    const int M = B * TOKENS;

    float* qkv_ptr; cudaGetSymbolAddress((void**)&qkv_ptr, g_qkv);
    float* y_ptr;   cudaGetSymbolAddress((void**)&y_ptr,   g_y);

    // 1) QKV projection
    {
        dim3 grid(QKV_DIM / 128, M / 128);
        tf32_gemm_bias_kernel<<<grid, 128>>>(x, wqkv_w, wqkv_b, qkv_ptr,
                                             M, QKV_DIM, C_DIM);
    }
    // 2) window attention
    {
        dim3 grid(B * 1024, N_HEADS);
        win_attn_kernel<<<grid, 64>>>(bias_table);
    }
    // 3) output projection
    {
        dim3 grid(C_DIM / 128, M / 128);
        tf32_gemm_bias_kernel<<<grid, 128>>>(y_ptr, wp_w, wp_b, (float*)d_out,
                                             M, C_DIM, C_DIM);
    }
}

// round 9
// speedup vs baseline: 1.0589x; 1.0589x over previous
#include <cuda_runtime.h>
#include <cstdint>

// ---------------------------------------------------------------------------
// SpatialWindowSelfAttention (Swin window MHSA), sm_103a — Round 9
//   1) TF32 GEMM: BK=32, 64x64 warp tile, double-buffered smem,
//      split A/B register prefetch, ONE sync per k-tile
//   2) window attention: coalesced coop I/O, f32x2 QK + f32x2 PV
//   3) same GEMM -> d_out
// ---------------------------------------------------------------------------

#define C_DIM    256
#define QKV_DIM  768
#define N_HEADS  8
#define HEAD_DIM 32
#define IMG      256
#define TOKENS   (IMG * IMG)
#define WS       64
#define MAX_B    2

__device__ float g_qkv[MAX_B * TOKENS * QKV_DIM];
__device__ float g_y  [MAX_B * TOKENS * C_DIM];

// ---------------------------------------------------------------------------
__device__ __forceinline__ uint32_t f2tf32(float x) {
    uint32_t r;
    asm("cvt.rna.tf32.f32 %0, %1;" : "=r"(r) : "f"(x));
    return r;
}

__device__ __forceinline__ void mma_tf32(float* d, const uint32_t* a, const uint32_t* b) {
    asm volatile(
        "mma.sync.aligned.m16n8k8.row.col.f32.tf32.tf32.f32 "
        "{%0,%1,%2,%3}, {%4,%5,%6,%7}, {%8,%9}, {%0,%1,%2,%3};\n"
        : "+f"(d[0]), "+f"(d[1]), "+f"(d[2]), "+f"(d[3])
        : "r"(a[0]), "r"(a[1]), "r"(a[2]), "r"(a[3]),
          "r"(b[0]), "r"(b[1]));
}

// packed fp32x2 helpers
__device__ __forceinline__ uint64_t pack2(float lo, float hi) {
    uint64_t r; asm("mov.b64 %0, {%1, %2};" : "=l"(r) : "f"(lo), "f"(hi)); return r;
}
__device__ __forceinline__ void unpack2(uint64_t v, float& lo, float& hi) {
    asm("mov.b64 {%0, %1}, %2;" : "=f"(lo), "=f"(hi) : "l"(v));
}
__device__ __forceinline__ uint64_t fma2(uint64_t a, uint64_t b, uint64_t c) {
    uint64_t d; asm("fma.rn.f32x2 %0, %1, %2, %3;" : "=l"(d) : "l"(a), "l"(b), "l"(c));
    return d;
}

// ---------------------------------------------------------------------------
// TF32 GEMM: C[M,N] = A[M,K] @ Bw[N,K]^T + bias[N]
// BM=BN=128, BK=32. 128 threads = 4 warps (2 M x 2 N), warp tile 64x64.
// Double-buffered dynamic smem (2 x 36 KB), one __syncthreads per tile.
// Split prefetch: LDG A(next) before MMA ks0-1, LDG B(next) before ks2-3,
// STS after all MMAs -> LDG latency hides under the tensor section.
// Smem rows stride 36 (36 % 32 == 4): fragment banks 4g+t, conflict-free.
// ---------------------------------------------------------------------------
#define LDS_S 36
#define STAGE_WORDS (2 * 128 * LDS_S)     // A + B per buffer = 9216 words

__global__ __launch_bounds__(128, 2)
void tf32_gemm_bias_kernel(const float* __restrict__ A,
                           const float* __restrict__ Bw,
                           const float* __restrict__ bias,
                           float* __restrict__ C,
                           int M, int N, int K)
{
    constexpr int BK = 32;
    extern __shared__ uint32_t smem[];

    const int tid  = threadIdx.x;
    const int lane = tid & 31;
    const int wid  = tid >> 5;
    const int wm   = (wid & 1) * 64;
    const int wn   = (wid >> 1) * 64;
    const int m0   = blockIdx.y * 128;
    const int n0   = blockIdx.x * 128;
    const int t    = lane & 3;
    const int g    = lane >> 2;

    // staging slots: 8 float4 per thread per tile; row = (tid>>3)+16i, kc fixed
    const int srow = tid >> 3;
    const int skc  = (tid & 7) * 4;

    float acc[4][8][4];
    #pragma unroll
    for (int i = 0; i < 4; i++)
        #pragma unroll
        for (int j = 0; j < 8; j++)
            #pragma unroll
            for (int r = 0; r < 4; r++) acc[i][j][r] = 0.f;

    const int NT = K / BK;

    // prologue: stage tile 0 into buffer 0 (interleaved LDG/CVT/STS)
    {
        uint32_t* As0 = smem;
        uint32_t* Bs0 = smem + 128 * LDS_S;
        #pragma unroll
        for (int i = 0; i < 8; i++) {
            int row = srow + i * 16;
            float4 va = *(const float4*)(A  + (size_t)(m0 + row) * K + skc);
            float4 vb = *(const float4*)(Bw + (size_t)(n0 + row) * K + skc);
            *(uint4*)&As0[row * LDS_S + skc] =
                make_uint4(f2tf32(va.x), f2tf32(va.y), f2tf32(va.z), f2tf32(va.w));
            *(uint4*)&Bs0[row * LDS_S + skc] =
                make_uint4(f2tf32(vb.x), f2tf32(vb.y), f2tf32(vb.z), f2tf32(vb.w));
        }
    }
    __syncthreads();

    for (int kt = 0; kt < NT; kt++) {
        const uint32_t* As = smem + (kt & 1) * STAGE_WORDS;
        const uint32_t* Bs = As + 128 * LDS_S;
        uint32_t* Asn = smem + ((kt + 1) & 1) * STAGE_WORDS;
        uint32_t* Bsn = Asn + 128 * LDS_S;
        const bool pf = (kt + 1 < NT);
        const int kn = (kt + 1) * BK;

        float4 pa[8], pb[8];

        // prefetch A(next); latency hides under ks=0,1 MMAs
        if (pf) {
            #pragma unroll
            for (int i = 0; i < 8; i++) {
                int row = srow + i * 16;
                pa[i] = *(const float4*)(A + (size_t)(m0 + row) * K + kn + skc);
            }
        }

        #pragma unroll
        for (int ks = 0; ks < 2; ks++) {
            const int kb = ks * 8;
            uint32_t a[4][4], b[8][2];
            #pragma unroll
            for (int mf = 0; mf < 4; mf++) {
                int r = wm + mf * 16 + g;
                a[mf][0] = As[(r    ) * LDS_S + kb + t];
                a[mf][1] = As[(r + 8) * LDS_S + kb + t];
                a[mf][2] = As[(r    ) * LDS_S + kb + t + 4];
                a[mf][3] = As[(r + 8) * LDS_S + kb + t + 4];
            }
            #pragma unroll
            for (int nf = 0; nf < 8; nf++) {
                int n = wn + nf * 8 + g;
                b[nf][0] = Bs[n * LDS_S + kb + t];
                b[nf][1] = Bs[n * LDS_S + kb + t + 4];
            }
            #pragma unroll
            for (int mf = 0; mf < 4; mf++)
                #pragma unroll
                for (int nf = 0; nf < 8; nf++)
                    mma_tf32(acc[mf][nf], a[mf], b[nf]);
        }

        // prefetch B(next); latency hides under ks=2,3 MMAs
        if (pf) {
            #pragma unroll
            for (int i = 0; i < 8; i++) {
                int row = srow + i * 16;
                pb[i] = *(const float4*)(Bw + (size_t)(n0 + row) * K + kn + skc);
            }
        }

        #pragma unroll
        for (int ks = 2; ks < 4; ks++) {
            const int kb = ks * 8;
            uint32_t a[4][4], b[8][2];
            #pragma unroll
            for (int mf = 0; mf < 4; mf++) {
                int r = wm + mf * 16 + g;
                a[mf][0] = As[(r    ) * LDS_S + kb + t];
                a[mf][1] = As[(r + 8) * LDS_S + kb + t];
                a[mf][2] = As[(r    ) * LDS_S + kb + t + 4];
                a[mf][3] = As[(r + 8) * LDS_S + kb + t + 4];
            }
            #pragma unroll
            for (int nf = 0; nf < 8; nf++) {
                int n = wn + nf * 8 + g;
                b[nf][0] = Bs[n * LDS_S + kb + t];
                b[nf][1] = Bs[n * LDS_S + kb + t + 4];
            }
            #pragma unroll
            for (int mf = 0; mf < 4; mf++)
                #pragma unroll
                for (int nf = 0; nf < 8; nf++)
                    mma_tf32(acc[mf][nf], a[mf], b[nf]);
        }

        // store prefetched tile into the other buffer
        if (pf) {
            #pragma unroll
            for (int i = 0; i < 8; i++) {
                int row = srow + i * 16;
                *(uint4*)&Asn[row * LDS_S + skc] =
                    make_uint4(f2tf32(pa[i].x), f2tf32(pa[i].y),
                               f2tf32(pa[i].z), f2tf32(pa[i].w));
                *(uint4*)&Bsn[row * LDS_S + skc] =
                    make_uint4(f2tf32(pb[i].x), f2tf32(pb[i].y),
                               f2tf32(pb[i].z), f2tf32(pb[i].w));
            }
        }
        __syncthreads();
    }

    // epilogue: bias + store
    #pragma unroll
    for (int mf = 0; mf < 4; mf++) {
        int row = m0 + wm + mf * 16 + g;
        #pragma unroll
        for (int nf = 0; nf < 8; nf++) {
            int col = n0 + wn + nf * 8 + 2 * t;
            float bx = bias[col], by = bias[col + 1];
            float2 v0 = make_float2(acc[mf][nf][0] + bx, acc[mf][nf][1] + by);
            float2 v1 = make_float2(acc[mf][nf][2] + bx, acc[mf][nf][3] + by);
            *(float2*)(C + (size_t)row * N + col)       = v0;
            *(float2*)(C + (size_t)(row + 8) * N + col) = v1;
        }
    }
}

// ---------------------------------------------------------------------------
// Window attention: block = (window, head), 64 threads.
// Coalesced coop I/O; QK and PV both use packed fma.rn.f32x2.
// ---------------------------------------------------------------------------
__global__ __launch_bounds__(64)
void win_attn_kernel(const float* __restrict__ bias_table)
{
    __shared__ float Qs[WS][HEAD_DIM];
    __shared__ float Ks[WS][HEAD_DIM];
    __shared__ float Vs[WS][HEAD_DIM];
    __shared__ float bias_s[225];

    const int t    = threadIdx.x;
    const int head = blockIdx.y;
    const int bi   = blockIdx.x >> 10;
    const int wid  = blockIdx.x & 1023;
    const int wy   = wid >> 5, wx = wid & 31;

    #pragma unroll
    for (int i = 0; i < 8; i++) {
        int slot = t + i * 64;
        int j    = slot >> 3;
        int f    = slot & 7;
        int jr = j >> 3, jc = j & 7;
        size_t tok = (size_t)bi * TOKENS + (size_t)(wy * 8 + jr) * IMG + (wx * 8 + jc);
        const float4* base = (const float4*)(g_qkv + tok * QKV_DIM + head * HEAD_DIM);
        *(float4*)&Qs[j][f * 4] = base[f];
        *(float4*)&Ks[j][f * 4] = base[f + C_DIM / 4];
        *(float4*)&Vs[j][f * 4] = base[f + 2 * C_DIM / 4];
    }
    for (int i = t; i < 225; i += 64)
        bias_s[i] = bias_table[i * N_HEADS + head];
    __syncthreads();

    const int r = t >> 3, c = t & 7;

    uint64_t q2[HEAD_DIM / 2];
    #pragma unroll
    for (int d2 = 0; d2 < HEAD_DIM / 2; d2++)
        q2[d2] = *(const uint64_t*)&Qs[t][2 * d2];

    const float scale = 0.17677669529663689f;   // 1/sqrt(32)
    float s[WS];
    #pragma unroll
    for (int k = 0; k < WS; k++) {
        const uint64_t* k2 = (const uint64_t*)Ks[k];
        uint64_t a0 = 0ull, a1 = 0ull;
        #pragma unroll
        for (int d2 = 0; d2 < HEAD_DIM / 2; d2 += 2) {
            a0 = fma2(q2[d2    ], k2[d2    ], a0);
            a1 = fma2(q2[d2 + 1], k2[d2 + 1], a1);
        }
        float l0, h0, l1, h1;
        unpack2(a0, l0, h0); unpack2(a1, l1, h1);
        float dot = (l0 + h0) + (l1 + h1);
        int ki = k >> 3, kj = k & 7;
        s[k] = dot * scale + bias_s[(r - ki + 7) * 15 + (c - kj + 7)];
    }

    float m = -1e30f;
    #pragma unroll
    for (int k = 0; k < WS; k++) m = fmaxf(m, s[k]);
    float sum = 0.f;
    #pragma unroll
    for (int k = 0; k < WS; k++) { s[k] = __expf(s[k] - m); sum += s[k]; }
    const float inv = 1.f / sum;

    // PV with packed f32x2 (broadcast p, pairwise V)
    uint64_t y2[HEAD_DIM / 2];
    #pragma unroll
    for (int d2 = 0; d2 < HEAD_DIM / 2; d2++) y2[d2] = 0ull;
    #pragma unroll
    for (int k = 0; k < WS; k++) {
        uint64_t p2 = pack2(s[k], s[k]);
        const uint64_t* v2 = (const uint64_t*)Vs[k];
        #pragma unroll
        for (int d2 = 0; d2 < HEAD_DIM / 2; d2++)
            y2[d2] = fma2(p2, v2[d2], y2[d2]);
    }

    // stage output in smem (reuse Qs), then coalesced cooperative store
    __syncthreads();
    #pragma unroll
    for (int d2 = 0; d2 < HEAD_DIM / 2; d2++) {
        float lo, hi; unpack2(y2[d2], lo, hi);
        Qs[t][2 * d2    ] = lo * inv;
        Qs[t][2 * d2 + 1] = hi * inv;
    }
    __syncthreads();

    #pragma unroll
    for (int i = 0; i < 8; i++) {
        int slot = t + i * 64;
        int j    = slot >> 3;
        int f    = slot & 7;
        int jr = j >> 3, jc = j & 7;
        size_t tok = (size_t)bi * TOKENS + (size_t)(wy * 8 + jr) * IMG + (wx * 8 + jc);
        float4* dst = (float4*)(g_y + tok * C_DIM + head * HEAD_DIM);
        dst[f] = *(const float4*)&Qs[j][f * 4];
    }
}

// ---------------------------------------------------------------------------
extern "C" void kernel_launch(void* const* d_in, const int* in_sizes, int n_in,
                              void* d_out, int out_size)
{
    const float *x = nullptr, *wqkv_w = nullptr, *wqkv_b = nullptr;
    const float *wp_w = nullptr, *wp_b = nullptr, *bias_table = nullptr;
    long long x_elems = 0;
    for (int i = 0; i < n_in; i++) {
        long long sz = in_sizes[i];
        if      (sz == 768LL * 256)  wqkv_w = (const float*)d_in[i];
        else if (sz == 768)          wqkv_b = (const float*)d_in[i];
        else if (sz == 256LL * 256)  wp_w   = (const float*)d_in[i];
        else if (sz == 256)          wp_b   = (const float*)d_in[i];
        else if (sz == 225LL * 8)    bias_table = (const float*)d_in[i];
        else if (sz > 1000000)       { x = (const float*)d_in[i]; x_elems = sz; }
    }

    const int B = (int)(x_elems / ((long long)TOKENS * C_DIM));   // = 2
    const int M = B * TOKENS;

    float* qkv_ptr; cudaGetSymbolAddress((void**)&qkv_ptr, g_qkv);
    float* y_ptr;   cudaGetSymbolAddress((void**)&y_ptr,   g_y);

    const int smem_bytes = 2 * STAGE_WORDS * (int)sizeof(uint32_t);   // 73728
    static bool attr_set = false;
    if (!attr_set) {
        cudaFuncSetAttribute(tf32_gemm_bias_kernel,
                             cudaFuncAttributeMaxDynamicSharedMemorySize, smem_bytes);
        attr_set = true;
    }

    // 1) QKV projection
    {
        dim3 grid(QKV_DIM / 128, M / 128);
        tf32_gemm_bias_kernel<<<grid, 128, smem_bytes>>>(x, wqkv_w, wqkv_b, qkv_ptr,
                                                         M, QKV_DIM, C_DIM);
    }
    // 2) window attention
    {
        dim3 grid(B * 1024, N_HEADS);
        win_attn_kernel<<<grid, 64>>>(bias_table);
    }
    // 3) output projection
    {
        dim3 grid(C_DIM / 128, M / 128);
        tf32_gemm_bias_kernel<<<grid, 128, smem_bytes>>>(y_ptr, wp_w, wp_b, (float*)d_out,
                                                         M, C_DIM, C_DIM);
    }
}

// round 10
// speedup vs baseline: 1.3220x; 1.2485x over previous
#include <cuda_runtime.h>
#include <cstdint>

// ---------------------------------------------------------------------------
// SpatialWindowSelfAttention (Swin window MHSA), sm_103a — Round 10
//   1) TF32 GEMM (R9: BK=32, 64x64 warp tile, double-buffer, split prefetch)
//   2) TENSOR-CORE window attention: warp = (window, head), QK and PV via
//      mma.m16n8k8.tf32; softmax on C-fragments with quad shuffles;
//      P C-layout -> A-layout via intra-quad shuffles (no smem roundtrip)
//   3) same GEMM -> d_out
// ---------------------------------------------------------------------------

#define C_DIM    256
#define QKV_DIM  768
#define N_HEADS  8
#define HEAD_DIM 32
#define IMG      256
#define TOKENS   (IMG * IMG)
#define WS       64
#define MAX_B    2

__device__ float g_qkv[MAX_B * TOKENS * QKV_DIM];
__device__ float g_y  [MAX_B * TOKENS * C_DIM];

// ---------------------------------------------------------------------------
__device__ __forceinline__ uint32_t f2tf32(float x) {
    uint32_t r;
    asm("cvt.rna.tf32.f32 %0, %1;" : "=r"(r) : "f"(x));
    return r;
}

__device__ __forceinline__ void mma_tf32(float* d, const uint32_t* a, const uint32_t* b) {
    asm volatile(
        "mma.sync.aligned.m16n8k8.row.col.f32.tf32.tf32.f32 "
        "{%0,%1,%2,%3}, {%4,%5,%6,%7}, {%8,%9}, {%0,%1,%2,%3};\n"
        : "+f"(d[0]), "+f"(d[1]), "+f"(d[2]), "+f"(d[3])
        : "r"(a[0]), "r"(a[1]), "r"(a[2]), "r"(a[3]),
          "r"(b[0]), "r"(b[1]));
}

// ---------------------------------------------------------------------------
// TF32 GEMM (unchanged from Round 9 — measured best at 365us for QKV)
// ---------------------------------------------------------------------------
#define LDS_S 36
#define STAGE_WORDS (2 * 128 * LDS_S)

__global__ __launch_bounds__(128, 2)
void tf32_gemm_bias_kernel(const float* __restrict__ A,
                           const float* __restrict__ Bw,
                           const float* __restrict__ bias,
                           float* __restrict__ C,
                           int M, int N, int K)
{
    constexpr int BK = 32;
    extern __shared__ uint32_t smem[];

    const int tid  = threadIdx.x;
    const int lane = tid & 31;
    const int wid  = tid >> 5;
    const int wm   = (wid & 1) * 64;
    const int wn   = (wid >> 1) * 64;
    const int m0   = blockIdx.y * 128;
    const int n0   = blockIdx.x * 128;
    const int t    = lane & 3;
    const int g    = lane >> 2;

    const int srow = tid >> 3;
    const int skc  = (tid & 7) * 4;

    float acc[4][8][4];
    #pragma unroll
    for (int i = 0; i < 4; i++)
        #pragma unroll
        for (int j = 0; j < 8; j++)
            #pragma unroll
            for (int r = 0; r < 4; r++) acc[i][j][r] = 0.f;

    const int NT = K / BK;

    {
        uint32_t* As0 = smem;
        uint32_t* Bs0 = smem + 128 * LDS_S;
        #pragma unroll
        for (int i = 0; i < 8; i++) {
            int row = srow + i * 16;
            float4 va = *(const float4*)(A  + (size_t)(m0 + row) * K + skc);
            float4 vb = *(const float4*)(Bw + (size_t)(n0 + row) * K + skc);
            *(uint4*)&As0[row * LDS_S + skc] =
                make_uint4(f2tf32(va.x), f2tf32(va.y), f2tf32(va.z), f2tf32(va.w));
            *(uint4*)&Bs0[row * LDS_S + skc] =
                make_uint4(f2tf32(vb.x), f2tf32(vb.y), f2tf32(vb.z), f2tf32(vb.w));
        }
    }
    __syncthreads();

    for (int kt = 0; kt < NT; kt++) {
        const uint32_t* As = smem + (kt & 1) * STAGE_WORDS;
        const uint32_t* Bs = As + 128 * LDS_S;
        uint32_t* Asn = smem + ((kt + 1) & 1) * STAGE_WORDS;
        uint32_t* Bsn = Asn + 128 * LDS_S;
        const bool pf = (kt + 1 < NT);
        const int kn = (kt + 1) * BK;

        float4 pa[8], pb[8];

        if (pf) {
            #pragma unroll
            for (int i = 0; i < 8; i++) {
                int row = srow + i * 16;
                pa[i] = *(const float4*)(A + (size_t)(m0 + row) * K + kn + skc);
            }
        }

        #pragma unroll
        for (int ks = 0; ks < 2; ks++) {
            const int kb = ks * 8;
            uint32_t a[4][4], b[8][2];
            #pragma unroll
            for (int mf = 0; mf < 4; mf++) {
                int r = wm + mf * 16 + g;
                a[mf][0] = As[(r    ) * LDS_S + kb + t];
                a[mf][1] = As[(r + 8) * LDS_S + kb + t];
                a[mf][2] = As[(r    ) * LDS_S + kb + t + 4];
                a[mf][3] = As[(r + 8) * LDS_S + kb + t + 4];
            }
            #pragma unroll
            for (int nf = 0; nf < 8; nf++) {
                int n = wn + nf * 8 + g;
                b[nf][0] = Bs[n * LDS_S + kb + t];
                b[nf][1] = Bs[n * LDS_S + kb + t + 4];
            }
            #pragma unroll
            for (int mf = 0; mf < 4; mf++)
                #pragma unroll
                for (int nf = 0; nf < 8; nf++)
                    mma_tf32(acc[mf][nf], a[mf], b[nf]);
        }

        if (pf) {
            #pragma unroll
            for (int i = 0; i < 8; i++) {
                int row = srow + i * 16;
                pb[i] = *(const float4*)(Bw + (size_t)(n0 + row) * K + kn + skc);
            }
        }

        #pragma unroll
        for (int ks = 2; ks < 4; ks++) {
            const int kb = ks * 8;
            uint32_t a[4][4], b[8][2];
            #pragma unroll
            for (int mf = 0; mf < 4; mf++) {
                int r = wm + mf * 16 + g;
                a[mf][0] = As[(r    ) * LDS_S + kb + t];
                a[mf][1] = As[(r + 8) * LDS_S + kb + t];
                a[mf][2] = As[(r    ) * LDS_S + kb + t + 4];
                a[mf][3] = As[(r + 8) * LDS_S + kb + t + 4];
            }
            #pragma unroll
            for (int nf = 0; nf < 8; nf++) {
                int n = wn + nf * 8 + g;
                b[nf][0] = Bs[n * LDS_S + kb + t];
                b[nf][1] = Bs[n * LDS_S + kb + t + 4];
            }
            #pragma unroll
            for (int mf = 0; mf < 4; mf++)
                #pragma unroll
                for (int nf = 0; nf < 8; nf++)
                    mma_tf32(acc[mf][nf], a[mf], b[nf]);
        }

        if (pf) {
            #pragma unroll
            for (int i = 0; i < 8; i++) {
                int row = srow + i * 16;
                *(uint4*)&Asn[row * LDS_S + skc] =
                    make_uint4(f2tf32(pa[i].x), f2tf32(pa[i].y),
                               f2tf32(pa[i].z), f2tf32(pa[i].w));
                *(uint4*)&Bsn[row * LDS_S + skc] =
                    make_uint4(f2tf32(pb[i].x), f2tf32(pb[i].y),
                               f2tf32(pb[i].z), f2tf32(pb[i].w));
            }
        }
        __syncthreads();
    }

    #pragma unroll
    for (int mf = 0; mf < 4; mf++) {
        int row = m0 + wm + mf * 16 + g;
        #pragma unroll
        for (int nf = 0; nf < 8; nf++) {
            int col = n0 + wn + nf * 8 + 2 * t;
            float bx = bias[col], by = bias[col + 1];
            float2 v0 = make_float2(acc[mf][nf][0] + bx, acc[mf][nf][1] + by);
            float2 v1 = make_float2(acc[mf][nf][2] + bx, acc[mf][nf][3] + by);
            *(float2*)(C + (size_t)row * N + col)       = v0;
            *(float2*)(C + (size_t)(row + 8) * N + col) = v1;
        }
    }
}

// ---------------------------------------------------------------------------
// Tensor-core window attention.
// Block = (window, head-group of 4). 128 threads, warp w handles head hg*4+w.
// Smem (dynamic, words):
//   Qs[4][64][36] tf32 | Ks[4][64][36] tf32 | Vt[4][32][68] tf32 (transposed)
//   bias[4][225] f32
// Per warp: QK = m64n64k32 (2 half-passes of m32), softmax on C-frags,
// P->A-frag via intra-quad shuffles, PV = m32n32k64 per half.
// ---------------------------------------------------------------------------
#define AQ_OFF   0
#define AQ_HS    (64 * 36)              // 2304
#define AK_OFF   (4 * AQ_HS)            // 9216
#define AV_OFF   (AK_OFF + 4 * AQ_HS)   // 18432
#define AV_HS    (32 * 68)              // 2176
#define AB_OFF   (AV_OFF + 4 * AV_HS)   // 27136
#define ATTN_SMEM_WORDS (AB_OFF + 4 * 225)
#define ATTN_SMEM_BYTES (ATTN_SMEM_WORDS * 4)

__global__ __launch_bounds__(128, 2)
void win_attn_tc_kernel(const float* __restrict__ bias_table)
{
    extern __shared__ uint32_t smem[];

    const int tid  = threadIdx.x;
    const int lane = tid & 31;
    const int w    = tid >> 5;           // warp = head within group
    const int hg   = blockIdx.y;         // head group (0/1)
    const int bi   = blockIdx.x >> 10;
    const int widx = blockIdx.x & 1023;
    const int wy   = widx >> 5, wx = widx & 31;
    const int t    = lane & 3;
    const int g    = lane >> 2;

    // ---- cooperative staging: all 4 heads' Q, K, V(transposed) ----
    #pragma unroll
    for (int i = 0; i < 4; i++) {
        int slot = tid + i * 128;        // 0..511
        int j    = slot >> 3;            // token in window
        int f    = slot & 7;             // float4 within 32-dim head row
        int jr = j >> 3, jc = j & 7;
        size_t tok = (size_t)bi * TOKENS + (size_t)(wy * 8 + jr) * IMG + (wx * 8 + jc);
        const float* tb = g_qkv + tok * QKV_DIM;
        #pragma unroll
        for (int hh = 0; hh < 4; hh++) {
            int head = hg * 4 + hh;
            float4 qv = *(const float4*)(tb + head * 32 + f * 4);
            float4 kv = *(const float4*)(tb + 256 + head * 32 + f * 4);
            float4 vv = *(const float4*)(tb + 512 + head * 32 + f * 4);
            *(uint4*)&smem[AQ_OFF + hh * AQ_HS + j * 36 + f * 4] =
                make_uint4(f2tf32(qv.x), f2tf32(qv.y), f2tf32(qv.z), f2tf32(qv.w));
            *(uint4*)&smem[AK_OFF + hh * AQ_HS + j * 36 + f * 4] =
                make_uint4(f2tf32(kv.x), f2tf32(kv.y), f2tf32(kv.z), f2tf32(kv.w));
            int d0 = f * 4;
            uint32_t* vt = smem + AV_OFF + hh * AV_HS;
            vt[(d0 + 0) * 68 + j] = f2tf32(vv.x);
            vt[(d0 + 1) * 68 + j] = f2tf32(vv.y);
            vt[(d0 + 2) * 68 + j] = f2tf32(vv.z);
            vt[(d0 + 3) * 68 + j] = f2tf32(vv.w);
        }
    }
    for (int idx = tid; idx < 4 * 225; idx += 128) {
        int hh = idx / 225, i = idx - hh * 225;
        ((float*)(smem + AB_OFF))[hh * 225 + i] = bias_table[i * N_HEADS + hg * 4 + hh];
    }
    __syncthreads();

    const uint32_t* Qh = smem + AQ_OFF + w * AQ_HS;
    const uint32_t* Kh = smem + AK_OFF + w * AQ_HS;
    const uint32_t* Vh = smem + AV_OFF + w * AV_HS;
    const float*    bh = (const float*)(smem + AB_OFF) + w * 225;
    const int head = hg * 4 + w;
    const float scale = 0.17677669529663689f;   // 1/sqrt(32)

    const int srcA = (lane & ~3) | (t >> 1);
    const int srcB = srcA + 2;
    const bool podd = (t & 1) != 0;

    #pragma unroll
    for (int half = 0; half < 2; half++) {
        const int rbase = half * 32;

        // Q A-fragments for this half's 32 rows
        uint32_t qa[2][4][4];
        #pragma unroll
        for (int mf = 0; mf < 2; mf++)
            #pragma unroll
            for (int ks = 0; ks < 4; ks++) {
                int r = rbase + mf * 16 + g;
                qa[mf][ks][0] = Qh[(r    ) * 36 + ks * 8 + t];
                qa[mf][ks][1] = Qh[(r + 8) * 36 + ks * 8 + t];
                qa[mf][ks][2] = Qh[(r    ) * 36 + ks * 8 + t + 4];
                qa[mf][ks][3] = Qh[(r + 8) * 36 + ks * 8 + t + 4];
            }

        // QK^T scores
        float sc[2][8][4];
        #pragma unroll
        for (int mf = 0; mf < 2; mf++)
            #pragma unroll
            for (int nf = 0; nf < 8; nf++)
                #pragma unroll
                for (int i = 0; i < 4; i++) sc[mf][nf][i] = 0.f;

        #pragma unroll
        for (int nf = 0; nf < 8; nf++) {
            #pragma unroll
            for (int ks = 0; ks < 4; ks++) {
                uint32_t kf[2];
                kf[0] = Kh[(nf * 8 + g) * 36 + ks * 8 + t];
                kf[1] = Kh[(nf * 8 + g) * 36 + ks * 8 + t + 4];
                mma_tf32(sc[0][nf], qa[0][ks], kf);
                mma_tf32(sc[1][nf], qa[1][ks], kf);
            }
        }

        // scale + relative-position bias
        #pragma unroll
        for (int mf = 0; mf < 2; mf++) {
            int qr0 = rbase + mf * 16 + g;
            int qr1 = qr0 + 8;
            int q0r = qr0 >> 3, q0c = qr0 & 7;
            int q1r = qr1 >> 3, q1c = qr1 & 7;
            #pragma unroll
            for (int nf = 0; nf < 8; nf++) {
                int c0 = nf * 8 + 2 * t, c1 = c0 + 1;
                int k0r = c0 >> 3, k0c = c0 & 7;
                int k1r = c1 >> 3, k1c = c1 & 7;
                sc[mf][nf][0] = sc[mf][nf][0] * scale + bh[(q0r - k0r + 7) * 15 + (q0c - k0c + 7)];
                sc[mf][nf][1] = sc[mf][nf][1] * scale + bh[(q0r - k1r + 7) * 15 + (q0c - k1c + 7)];
                sc[mf][nf][2] = sc[mf][nf][2] * scale + bh[(q1r - k0r + 7) * 15 + (q1c - k0c + 7)];
                sc[mf][nf][3] = sc[mf][nf][3] * scale + bh[(q1r - k1r + 7) * 15 + (q1c - k1c + 7)];
            }
        }

        // softmax per row (rows live in a quad: shfl.bfly 1,2), P *= inv, cvt tf32
        #pragma unroll
        for (int mf = 0; mf < 2; mf++) {
            float m0 = -1e30f, m1 = -1e30f;
            #pragma unroll
            for (int nf = 0; nf < 8; nf++) {
                m0 = fmaxf(m0, fmaxf(sc[mf][nf][0], sc[mf][nf][1]));
                m1 = fmaxf(m1, fmaxf(sc[mf][nf][2], sc[mf][nf][3]));
            }
            m0 = fmaxf(m0, __shfl_xor_sync(0xffffffffu, m0, 1));
            m0 = fmaxf(m0, __shfl_xor_sync(0xffffffffu, m0, 2));
            m1 = fmaxf(m1, __shfl_xor_sync(0xffffffffu, m1, 1));
            m1 = fmaxf(m1, __shfl_xor_sync(0xffffffffu, m1, 2));
            float s0 = 0.f, s1 = 0.f;
            #pragma unroll
            for (int nf = 0; nf < 8; nf++) {
                float e0 = __expf(sc[mf][nf][0] - m0); sc[mf][nf][0] = e0; s0 += e0;
                float e1 = __expf(sc[mf][nf][1] - m0); sc[mf][nf][1] = e1; s0 += e1;
                float e2 = __expf(sc[mf][nf][2] - m1); sc[mf][nf][2] = e2; s1 += e2;
                float e3 = __expf(sc[mf][nf][3] - m1); sc[mf][nf][3] = e3; s1 += e3;
            }
            s0 += __shfl_xor_sync(0xffffffffu, s0, 1);
            s0 += __shfl_xor_sync(0xffffffffu, s0, 2);
            s1 += __shfl_xor_sync(0xffffffffu, s1, 1);
            s1 += __shfl_xor_sync(0xffffffffu, s1, 2);
            float inv0 = 1.f / s0, inv1 = 1.f / s1;
            #pragma unroll
            for (int nf = 0; nf < 8; nf++) {
                sc[mf][nf][0] = __uint_as_float(f2tf32(sc[mf][nf][0] * inv0));
                sc[mf][nf][1] = __uint_as_float(f2tf32(sc[mf][nf][1] * inv0));
                sc[mf][nf][2] = __uint_as_float(f2tf32(sc[mf][nf][2] * inv1));
                sc[mf][nf][3] = __uint_as_float(f2tf32(sc[mf][nf][3] * inv1));
            }
        }

        // PV: A = P (via quad shuffles C-layout -> A-layout), B = Vt
        float ya[2][4][4];
        #pragma unroll
        for (int mf = 0; mf < 2; mf++)
            #pragma unroll
            for (int nf = 0; nf < 4; nf++)
                #pragma unroll
                for (int i = 0; i < 4; i++) ya[mf][nf][i] = 0.f;

        #pragma unroll
        for (int ks = 0; ks < 8; ks++) {
            uint32_t pa[2][4];
            #pragma unroll
            for (int mf = 0; mf < 2; mf++) {
                float e0 = __shfl_sync(0xffffffffu, sc[mf][ks][0], srcA);
                float o0 = __shfl_sync(0xffffffffu, sc[mf][ks][1], srcA);
                float e1 = __shfl_sync(0xffffffffu, sc[mf][ks][2], srcA);
                float o1 = __shfl_sync(0xffffffffu, sc[mf][ks][3], srcA);
                float e2 = __shfl_sync(0xffffffffu, sc[mf][ks][0], srcB);
                float o2 = __shfl_sync(0xffffffffu, sc[mf][ks][1], srcB);
                float e3 = __shfl_sync(0xffffffffu, sc[mf][ks][2], srcB);
                float o3 = __shfl_sync(0xffffffffu, sc[mf][ks][3], srcB);
                pa[mf][0] = __float_as_uint(podd ? o0 : e0);
                pa[mf][1] = __float_as_uint(podd ? o1 : e1);
                pa[mf][2] = __float_as_uint(podd ? o2 : e2);
                pa[mf][3] = __float_as_uint(podd ? o3 : e3);
            }
            #pragma unroll
            for (int nfr = 0; nfr < 4; nfr++) {
                uint32_t vb[2];
                vb[0] = Vh[(nfr * 8 + g) * 68 + ks * 8 + t];
                vb[1] = Vh[(nfr * 8 + g) * 68 + ks * 8 + t + 4];
                mma_tf32(ya[0][nfr], pa[0], vb);
                mma_tf32(ya[1][nfr], pa[1], vb);
            }
        }

        // store y fragments to g_y
        #pragma unroll
        for (int mf = 0; mf < 2; mf++) {
            int wr0 = rbase + mf * 16 + g;
            int wr1 = wr0 + 8;
            size_t tok0 = (size_t)bi * TOKENS
                        + (size_t)(wy * 8 + (wr0 >> 3)) * IMG + (wx * 8 + (wr0 & 7));
            size_t tok1 = (size_t)bi * TOKENS
                        + (size_t)(wy * 8 + (wr1 >> 3)) * IMG + (wx * 8 + (wr1 & 7));
            #pragma unroll
            for (int nfr = 0; nfr < 4; nfr++) {
                int col = head * 32 + nfr * 8 + 2 * t;
                *(float2*)(g_y + tok0 * C_DIM + col) =
                    make_float2(ya[mf][nfr][0], ya[mf][nfr][1]);
                *(float2*)(g_y + tok1 * C_DIM + col) =
                    make_float2(ya[mf][nfr][2], ya[mf][nfr][3]);
            }
        }
    }
}

// ---------------------------------------------------------------------------
extern "C" void kernel_launch(void* const* d_in, const int* in_sizes, int n_in,
                              void* d_out, int out_size)
{
    const float *x = nullptr, *wqkv_w = nullptr, *wqkv_b = nullptr;
    const float *wp_w = nullptr, *wp_b = nullptr, *bias_table = nullptr;
    long long x_elems = 0;
    for (int i = 0; i < n_in; i++) {
        long long sz = in_sizes[i];
        if      (sz == 768LL * 256)  wqkv_w = (const float*)d_in[i];
        else if (sz == 768)          wqkv_b = (const float*)d_in[i];
        else if (sz == 256LL * 256)  wp_w   = (const float*)d_in[i];
        else if (sz == 256)          wp_b   = (const float*)d_in[i];
        else if (sz == 225LL * 8)    bias_table = (const float*)d_in[i];
        else if (sz > 1000000)       { x = (const float*)d_in[i]; x_elems = sz; }
    }

    const int B = (int)(x_elems / ((long long)TOKENS * C_DIM));   // = 2
    const int M = B * TOKENS;

    float* qkv_ptr; cudaGetSymbolAddress((void**)&qkv_ptr, g_qkv);
    float* y_ptr;   cudaGetSymbolAddress((void**)&y_ptr,   g_y);

    const int gemm_smem = 2 * STAGE_WORDS * (int)sizeof(uint32_t);   // 73728
    static bool attr_set = false;
    if (!attr_set) {
        cudaFuncSetAttribute(tf32_gemm_bias_kernel,
                             cudaFuncAttributeMaxDynamicSharedMemorySize, gemm_smem);
        cudaFuncSetAttribute(win_attn_tc_kernel,
                             cudaFuncAttributeMaxDynamicSharedMemorySize, ATTN_SMEM_BYTES);
        attr_set = true;
    }

    // 1) QKV projection
    {
        dim3 grid(QKV_DIM / 128, M / 128);
        tf32_gemm_bias_kernel<<<grid, 128, gemm_smem>>>(x, wqkv_w, wqkv_b, qkv_ptr,
                                                        M, QKV_DIM, C_DIM);
    }
    // 2) tensor-core window attention
    {
        dim3 grid(B * 1024, 2);
        win_attn_tc_kernel<<<grid, 128, ATTN_SMEM_BYTES>>>(bias_table);
    }
    // 3) output projection
    {
        dim3 grid(C_DIM / 128, M / 128);
        tf32_gemm_bias_kernel<<<grid, 128, gemm_smem>>>(y_ptr, wp_w, wp_b, (float*)d_out,
                                                        M, C_DIM, C_DIM);
    }
}

// round 16
// speedup vs baseline: 1.4373x; 1.0872x over previous
#include <cuda_runtime.h>
#include <cstdint>

// ---------------------------------------------------------------------------
// SpatialWindowSelfAttention (Swin window MHSA), sm_103a — Round 16
//   0) weight pre-transform: fragment-ordered tf32 B tables (L2-resident)
//   1) TF32 GEMM: A via smem (R9 reg-prefetch), B via direct coalesced LDG
//      of fragment table from L2 — no B staging, half the crossbar traffic
//   2) tensor-core window attention (R10, measured ~190us)
//   3) same GEMM -> d_out
// NOTE: no tcgen05 — harness ptxas targets compute_103 (no 'a' features).
// ---------------------------------------------------------------------------

#define C_DIM    256
#define QKV_DIM  768
#define N_HEADS  8
#define HEAD_DIM 32
#define IMG      256
#define TOKENS   (IMG * IMG)
#define WS       64
#define MAX_B    2

__device__ float    g_qkv[MAX_B * TOKENS * QKV_DIM];
__device__ float    g_y  [MAX_B * TOKENS * C_DIM];
__device__ uint32_t g_wqf[QKV_DIM * C_DIM];     // frag-ordered tf32 Wqkv
__device__ uint32_t g_wpf[C_DIM * C_DIM];       // frag-ordered tf32 Wp

// ---------------------------------------------------------------------------
__device__ __forceinline__ uint32_t f2tf32(float x) {
    uint32_t r;
    asm("cvt.rna.tf32.f32 %0, %1;" : "=r"(r) : "f"(x));
    return r;
}

__device__ __forceinline__ void mma_tf32(float* d, const uint32_t* a, const uint32_t* b) {
    asm volatile(
        "mma.sync.aligned.m16n8k8.row.col.f32.tf32.tf32.f32 "
        "{%0,%1,%2,%3}, {%4,%5,%6,%7}, {%8,%9}, {%0,%1,%2,%3};\n"
        : "+f"(d[0]), "+f"(d[1]), "+f"(d[2]), "+f"(d[3])
        : "r"(a[0]), "r"(a[1]), "r"(a[2]), "r"(a[3]),
          "r"(b[0]), "r"(b[1]));
}

// ---------------------------------------------------------------------------
// Weight transform: W[N,256] f32 -> fragment-ordered tf32 table.
// word(nb, ksa, lane, hi) = tf32(W[(nb*8 + lane/4)*256 + ksa*8 + hi*4 + lane%4])
// layout: out[nb*2048 + ksa*64 + lane*2 + hi]; per (nb,ksa) a warp's 8
// fragment bytes are 256B contiguous -> coalesced LDG.64 in the GEMM.
// ---------------------------------------------------------------------------
__global__ __launch_bounds__(256)
void build_bfrag_kernel(const float* __restrict__ W, uint32_t* __restrict__ out,
                        int total)
{
    int idx = blockIdx.x * 256 + threadIdx.x;
    if (idx >= total) return;
    int hi   = idx & 1;
    int lane = (idx >> 1) & 31;
    int ksa  = (idx >> 6) & 31;
    int nb   = idx >> 11;
    int g = lane >> 2, t = lane & 3;
    out[idx] = f2tf32(W[(nb * 8 + g) * 256 + ksa * 8 + hi * 4 + t]);
}

// ---------------------------------------------------------------------------
// TF32 GEMM: C[M,N] = A[M,256] @ W^T + bias, W given as fragment table Bf.
// BM=BN=128. 128 threads = 4 warps (2M x 2N), warp tile 64x64. K=256 fixed.
// A: double-buffered smem (stride 36, conflict-free), R9 register prefetch.
// B: per-ks fragment LDG.64 from L2 table, double-buffered in regs (dist 1).
// ---------------------------------------------------------------------------
#define LDS_S 36

__global__ __launch_bounds__(128, 2)
void tf32_gemm_bldg_kernel(const float* __restrict__ A,
                           const uint32_t* __restrict__ Bf,
                           const float* __restrict__ bias,
                           float* __restrict__ C,
                           int M, int N)
{
    __shared__ uint32_t As[2][128 * LDS_S];

    const int tid  = threadIdx.x;
    const int lane = tid & 31;
    const int w    = tid >> 5;
    const int wm   = (w & 1) * 64;
    const int wn   = (w >> 1) * 64;
    const int m0   = blockIdx.y * 128;
    const int n0   = blockIdx.x * 128;
    const int t    = lane & 3;
    const int g    = lane >> 2;

    const int srow = tid >> 3;
    const int skc  = (tid & 7) * 4;

    // warp's fragment-table base (nb blocks of 2048 words), lane offset folded in
    const uint32_t* bfb = Bf + (size_t)((n0 + wn) >> 3) * 2048 + lane * 2;

    float acc[4][8][4];
    #pragma unroll
    for (int i = 0; i < 4; i++)
        #pragma unroll
        for (int j = 0; j < 8; j++)
            #pragma unroll
            for (int r = 0; r < 4; r++) acc[i][j][r] = 0.f;

    // stage A tile 0
    #pragma unroll
    for (int i = 0; i < 8; i++) {
        int row = srow + i * 16;
        float4 v = *(const float4*)(A + (size_t)(m0 + row) * 256 + skc);
        *(uint4*)&As[0][row * LDS_S + skc] =
            make_uint4(f2tf32(v.x), f2tf32(v.y), f2tf32(v.z), f2tf32(v.w));
    }
    __syncthreads();

    // B fragment ring (depth 2, prefetch distance 1); preload ksa = 0
    uint32_t bf[2][8][2];
    #pragma unroll
    for (int nf = 0; nf < 8; nf++) {
        uint2 v = *(const uint2*)(bfb + nf * 2048);
        bf[0][nf][0] = v.x; bf[0][nf][1] = v.y;
    }

    for (int kt = 0; kt < 8; kt++) {
        const uint32_t* cs = As[kt & 1];
        uint32_t*       ns = As[(kt + 1) & 1];
        const bool pf = (kt < 7);

        // A register prefetch for next tile (hides under MMA section)
        float4 pa[8];
        if (pf) {
            const float* ap = A + (size_t)m0 * 256 + (kt + 1) * 32 + skc;
            #pragma unroll
            for (int i = 0; i < 8; i++)
                pa[i] = *(const float4*)(ap + (size_t)(srow + i * 16) * 256);
        }

        #pragma unroll
        for (int ks = 0; ks < 4; ks++) {
            // prefetch B fragments for next ksa into the other ring slot
            const int ksa1 = kt * 4 + ks + 1;
            if (ksa1 < 32) {
                #pragma unroll
                for (int nf = 0; nf < 8; nf++) {
                    uint2 v = *(const uint2*)(bfb + nf * 2048 + ksa1 * 64);
                    bf[(ks + 1) & 1][nf][0] = v.x;
                    bf[(ks + 1) & 1][nf][1] = v.y;
                }
            }

            const int kb = ks * 8;
            uint32_t a[4][4];
            #pragma unroll
            for (int mf = 0; mf < 4; mf++) {
                int r = wm + mf * 16 + g;
                a[mf][0] = cs[(r    ) * LDS_S + kb + t];
                a[mf][1] = cs[(r + 8) * LDS_S + kb + t];
                a[mf][2] = cs[(r    ) * LDS_S + kb + t + 4];
                a[mf][3] = cs[(r + 8) * LDS_S + kb + t + 4];
            }
            #pragma unroll
            for (int mf = 0; mf < 4; mf++)
                #pragma unroll
                for (int nf = 0; nf < 8; nf++)
                    mma_tf32(acc[mf][nf], a[mf], bf[ks & 1][nf]);
        }

        // store A prefetch into the other buffer
        if (pf) {
            #pragma unroll
            for (int i = 0; i < 8; i++) {
                int row = srow + i * 16;
                *(uint4*)&ns[row * LDS_S + skc] =
                    make_uint4(f2tf32(pa[i].x), f2tf32(pa[i].y),
                               f2tf32(pa[i].z), f2tf32(pa[i].w));
            }
        }
        __syncthreads();
    }

    // epilogue: bias + store
    #pragma unroll
    for (int mf = 0; mf < 4; mf++) {
        int row = m0 + wm + mf * 16 + g;
        #pragma unroll
        for (int nf = 0; nf < 8; nf++) {
            int col = n0 + wn + nf * 8 + 2 * t;
            float bx = bias[col], by = bias[col + 1];
            float2 v0 = make_float2(acc[mf][nf][0] + bx, acc[mf][nf][1] + by);
            float2 v1 = make_float2(acc[mf][nf][2] + bx, acc[mf][nf][3] + by);
            *(float2*)(C + (size_t)row * N + col)       = v0;
            *(float2*)(C + (size_t)(row + 8) * N + col) = v1;
        }
    }
}

// ---------------------------------------------------------------------------
// Tensor-core window attention (R10, unchanged — measured ~190us)
// ---------------------------------------------------------------------------
#define AQ_OFF   0
#define AQ_HS    (64 * 36)
#define AK_OFF   (4 * AQ_HS)
#define AV_OFF   (AK_OFF + 4 * AQ_HS)
#define AV_HS    (32 * 68)
#define AB_OFF   (AV_OFF + 4 * AV_HS)
#define ATTN_SMEM_WORDS (AB_OFF + 4 * 225)
#define ATTN_SMEM_BYTES (ATTN_SMEM_WORDS * 4)

__global__ __launch_bounds__(128, 2)
void win_attn_tc_kernel(const float* __restrict__ bias_table)
{
    extern __shared__ uint32_t smem[];

    const int tid  = threadIdx.x;
    const int lane = tid & 31;
    const int w    = tid >> 5;
    const int hg   = blockIdx.y;
    const int bi   = blockIdx.x >> 10;
    const int widx = blockIdx.x & 1023;
    const int wy   = widx >> 5, wx = widx & 31;
    const int t    = lane & 3;
    const int g    = lane >> 2;

    #pragma unroll
    for (int i = 0; i < 4; i++) {
        int slot = tid + i * 128;
        int j    = slot >> 3;
        int f    = slot & 7;
        int jr = j >> 3, jc = j & 7;
        size_t tok = (size_t)bi * TOKENS + (size_t)(wy * 8 + jr) * IMG + (wx * 8 + jc);
        const float* tb = g_qkv + tok * QKV_DIM;
        #pragma unroll
        for (int hh = 0; hh < 4; hh++) {
            int head = hg * 4 + hh;
            float4 qv = *(const float4*)(tb + head * 32 + f * 4);
            float4 kv = *(const float4*)(tb + 256 + head * 32 + f * 4);
            float4 vv = *(const float4*)(tb + 512 + head * 32 + f * 4);
            *(uint4*)&smem[AQ_OFF + hh * AQ_HS + j * 36 + f * 4] =
                make_uint4(f2tf32(qv.x), f2tf32(qv.y), f2tf32(qv.z), f2tf32(qv.w));
            *(uint4*)&smem[AK_OFF + hh * AQ_HS + j * 36 + f * 4] =
                make_uint4(f2tf32(kv.x), f2tf32(kv.y), f2tf32(kv.z), f2tf32(kv.w));
            int d0 = f * 4;
            uint32_t* vt = smem + AV_OFF + hh * AV_HS;
            vt[(d0 + 0) * 68 + j] = f2tf32(vv.x);
            vt[(d0 + 1) * 68 + j] = f2tf32(vv.y);
            vt[(d0 + 2) * 68 + j] = f2tf32(vv.z);
            vt[(d0 + 3) * 68 + j] = f2tf32(vv.w);
        }
    }
    for (int idx = tid; idx < 4 * 225; idx += 128) {
        int hh = idx / 225, i = idx - hh * 225;
        ((float*)(smem + AB_OFF))[hh * 225 + i] = bias_table[i * N_HEADS + hg * 4 + hh];
    }
    __syncthreads();

    const uint32_t* Qh = smem + AQ_OFF + w * AQ_HS;
    const uint32_t* Kh = smem + AK_OFF + w * AQ_HS;
    const uint32_t* Vh = smem + AV_OFF + w * AV_HS;
    const float*    bh = (const float*)(smem + AB_OFF) + w * 225;
    const int head = hg * 4 + w;
    const float scale = 0.17677669529663689f;

    const int srcA = (lane & ~3) | (t >> 1);
    const int srcB = srcA + 2;
    const bool podd = (t & 1) != 0;

    #pragma unroll
    for (int half = 0; half < 2; half++) {
        const int rbase = half * 32;

        uint32_t qa[2][4][4];
        #pragma unroll
        for (int mf = 0; mf < 2; mf++)
            #pragma unroll
            for (int ks = 0; ks < 4; ks++) {
                int r = rbase + mf * 16 + g;
                qa[mf][ks][0] = Qh[(r    ) * 36 + ks * 8 + t];
                qa[mf][ks][1] = Qh[(r + 8) * 36 + ks * 8 + t];
                qa[mf][ks][2] = Qh[(r    ) * 36 + ks * 8 + t + 4];
                qa[mf][ks][3] = Qh[(r + 8) * 36 + ks * 8 + t + 4];
            }

        float sc[2][8][4];
        #pragma unroll
        for (int mf = 0; mf < 2; mf++)
            #pragma unroll
            for (int nf = 0; nf < 8; nf++)
                #pragma unroll
                for (int i = 0; i < 4; i++) sc[mf][nf][i] = 0.f;

        #pragma unroll
        for (int nf = 0; nf < 8; nf++) {
            #pragma unroll
            for (int ks = 0; ks < 4; ks++) {
                uint32_t kf[2];
                kf[0] = Kh[(nf * 8 + g) * 36 + ks * 8 + t];
                kf[1] = Kh[(nf * 8 + g) * 36 + ks * 8 + t + 4];
                mma_tf32(sc[0][nf], qa[0][ks], kf);
                mma_tf32(sc[1][nf], qa[1][ks], kf);
            }
        }

        #pragma unroll
        for (int mf = 0; mf < 2; mf++) {
            int qr0 = rbase + mf * 16 + g;
            int qr1 = qr0 + 8;
            int q0r = qr0 >> 3, q0c = qr0 & 7;
            int q1r = qr1 >> 3, q1c = qr1 & 7;
            #pragma unroll
            for (int nf = 0; nf < 8; nf++) {
                int c0 = nf * 8 + 2 * t, c1 = c0 + 1;
                int k0r = c0 >> 3, k0c = c0 & 7;
                int k1r = c1 >> 3, k1c = c1 & 7;
                sc[mf][nf][0] = sc[mf][nf][0] * scale + bh[(q0r - k0r + 7) * 15 + (q0c - k0c + 7)];
                sc[mf][nf][1] = sc[mf][nf][1] * scale + bh[(q0r - k1r + 7) * 15 + (q0c - k1c + 7)];
                sc[mf][nf][2] = sc[mf][nf][2] * scale + bh[(q1r - k0r + 7) * 15 + (q1c - k0c + 7)];
                sc[mf][nf][3] = sc[mf][nf][3] * scale + bh[(q1r - k1r + 7) * 15 + (q1c - k1c + 7)];
            }
        }

        #pragma unroll
        for (int mf = 0; mf < 2; mf++) {
            float m0 = -1e30f, m1 = -1e30f;
            #pragma unroll
            for (int nf = 0; nf < 8; nf++) {
                m0 = fmaxf(m0, fmaxf(sc[mf][nf][0], sc[mf][nf][1]));
                m1 = fmaxf(m1, fmaxf(sc[mf][nf][2], sc[mf][nf][3]));
            }
            m0 = fmaxf(m0, __shfl_xor_sync(0xffffffffu, m0, 1));
            m0 = fmaxf(m0, __shfl_xor_sync(0xffffffffu, m0, 2));
            m1 = fmaxf(m1, __shfl_xor_sync(0xffffffffu, m1, 1));
            m1 = fmaxf(m1, __shfl_xor_sync(0xffffffffu, m1, 2));
            float s0 = 0.f, s1 = 0.f;
            #pragma unroll
            for (int nf = 0; nf < 8; nf++) {
                float e0 = __expf(sc[mf][nf][0] - m0); sc[mf][nf][0] = e0; s0 += e0;
                float e1 = __expf(sc[mf][nf][1] - m0); sc[mf][nf][1] = e1; s0 += e1;
                float e2 = __expf(sc[mf][nf][2] - m1); sc[mf][nf][2] = e2; s1 += e2;
                float e3 = __expf(sc[mf][nf][3] - m1); sc[mf][nf][3] = e3; s1 += e3;
            }
            s0 += __shfl_xor_sync(0xffffffffu, s0, 1);
            s0 += __shfl_xor_sync(0xffffffffu, s0, 2);
            s1 += __shfl_xor_sync(0xffffffffu, s1, 1);
            s1 += __shfl_xor_sync(0xffffffffu, s1, 2);
            float inv0 = 1.f / s0, inv1 = 1.f / s1;
            #pragma unroll
            for (int nf = 0; nf < 8; nf++) {
                sc[mf][nf][0] = __uint_as_float(f2tf32(sc[mf][nf][0] * inv0));
                sc[mf][nf][1] = __uint_as_float(f2tf32(sc[mf][nf][1] * inv0));
                sc[mf][nf][2] = __uint_as_float(f2tf32(sc[mf][nf][2] * inv1));
                sc[mf][nf][3] = __uint_as_float(f2tf32(sc[mf][nf][3] * inv1));
            }
        }

        float ya[2][4][4];
        #pragma unroll
        for (int mf = 0; mf < 2; mf++)
            #pragma unroll
            for (int nf = 0; nf < 4; nf++)
                #pragma unroll
                for (int i = 0; i < 4; i++) ya[mf][nf][i] = 0.f;

        #pragma unroll
        for (int ks = 0; ks < 8; ks++) {
            uint32_t pa[2][4];
            #pragma unroll
            for (int mf = 0; mf < 2; mf++) {
                float e0 = __shfl_sync(0xffffffffu, sc[mf][ks][0], srcA);
                float o0 = __shfl_sync(0xffffffffu, sc[mf][ks][1], srcA);
                float e1 = __shfl_sync(0xffffffffu, sc[mf][ks][2], srcA);
                float o1 = __shfl_sync(0xffffffffu, sc[mf][ks][3], srcA);
                float e2 = __shfl_sync(0xffffffffu, sc[mf][ks][0], srcB);
                float o2 = __shfl_sync(0xffffffffu, sc[mf][ks][1], srcB);
                float e3 = __shfl_sync(0xffffffffu, sc[mf][ks][2], srcB);
                float o3 = __shfl_sync(0xffffffffu, sc[mf][ks][3], srcB);
                pa[mf][0] = __float_as_uint(podd ? o0 : e0);
                pa[mf][1] = __float_as_uint(podd ? o1 : e1);
                pa[mf][2] = __float_as_uint(podd ? o2 : e2);
                pa[mf][3] = __float_as_uint(podd ? o3 : e3);
            }
            #pragma unroll
            for (int nfr = 0; nfr < 4; nfr++) {
                uint32_t vb[2];
                vb[0] = Vh[(nfr * 8 + g) * 68 + ks * 8 + t];
                vb[1] = Vh[(nfr * 8 + g) * 68 + ks * 8 + t + 4];
                mma_tf32(ya[0][nfr], pa[0], vb);
                mma_tf32(ya[1][nfr], pa[1], vb);
            }
        }

        #pragma unroll
        for (int mf = 0; mf < 2; mf++) {
            int wr0 = rbase + mf * 16 + g;
            int wr1 = wr0 + 8;
            size_t tok0 = (size_t)bi * TOKENS
                        + (size_t)(wy * 8 + (wr0 >> 3)) * IMG + (wx * 8 + (wr0 & 7));
            size_t tok1 = (size_t)bi * TOKENS
                        + (size_t)(wy * 8 + (wr1 >> 3)) * IMG + (wx * 8 + (wr1 & 7));
            #pragma unroll
            for (int nfr = 0; nfr < 4; nfr++) {
                int col = head * 32 + nfr * 8 + 2 * t;
                *(float2*)(g_y + tok0 * C_DIM + col) =
                    make_float2(ya[mf][nfr][0], ya[mf][nfr][1]);
                *(float2*)(g_y + tok1 * C_DIM + col) =
                    make_float2(ya[mf][nfr][2], ya[mf][nfr][3]);
            }
        }
    }
}

// ---------------------------------------------------------------------------
extern "C" void kernel_launch(void* const* d_in, const int* in_sizes, int n_in,
                              void* d_out, int out_size)
{
    const float *x = nullptr, *wqkv_w = nullptr, *wqkv_b = nullptr;
    const float *wp_w = nullptr, *wp_b = nullptr, *bias_table = nullptr;
    long long x_elems = 0;
    for (int i = 0; i < n_in; i++) {
        long long sz = in_sizes[i];
        if      (sz == 768LL * 256)  wqkv_w = (const float*)d_in[i];
        else if (sz == 768)          wqkv_b = (const float*)d_in[i];
        else if (sz == 256LL * 256)  wp_w   = (const float*)d_in[i];
        else if (sz == 256)          wp_b   = (const float*)d_in[i];
        else if (sz == 225LL * 8)    bias_table = (const float*)d_in[i];
        else if (sz > 1000000)       { x = (const float*)d_in[i]; x_elems = sz; }
    }

    const int B = (int)(x_elems / ((long long)TOKENS * C_DIM));   // = 2
    const int M = B * TOKENS;

    float*    qkv_ptr; cudaGetSymbolAddress((void**)&qkv_ptr, g_qkv);
    float*    y_ptr;   cudaGetSymbolAddress((void**)&y_ptr,   g_y);
    uint32_t* wqf_ptr; cudaGetSymbolAddress((void**)&wqf_ptr, g_wqf);
    uint32_t* wpf_ptr; cudaGetSymbolAddress((void**)&wpf_ptr, g_wpf);

    static bool attr_set = false;
    if (!attr_set) {
        cudaFuncSetAttribute(win_attn_tc_kernel,
                             cudaFuncAttributeMaxDynamicSharedMemorySize, ATTN_SMEM_BYTES);
        attr_set = true;
    }

    // 0) weight fragment tables (tiny; L2-resident afterwards)
    build_bfrag_kernel<<<(QKV_DIM * C_DIM + 255) / 256, 256>>>(wqkv_w, wqf_ptr,
                                                               QKV_DIM * C_DIM);
    build_bfrag_kernel<<<(C_DIM * C_DIM + 255) / 256, 256>>>(wp_w, wpf_ptr,
                                                             C_DIM * C_DIM);

    // 1) QKV projection
    {
        dim3 grid(QKV_DIM / 128, M / 128);
        tf32_gemm_bldg_kernel<<<grid, 128>>>(x, wqf_ptr, wqkv_b, qkv_ptr,
                                             M, QKV_DIM);
    }
    // 2) tensor-core window attention
    {
        dim3 grid(B * 1024, 2);
        win_attn_tc_kernel<<<grid, 128, ATTN_SMEM_BYTES>>>(bias_table);
    }
    // 3) output projection
    {
        dim3 grid(C_DIM / 128, M / 128);
        tf32_gemm_bldg_kernel<<<grid, 128>>>(y_ptr, wpf_ptr, wp_b, (float*)d_out,
                                             M, C_DIM);
    }
}